// round 10
// baseline (speedup 1.0000x reference)
#include <cuda_runtime.h>
#include <cuda_fp16.h>
#include <cstdint>

// ===========================================================================
// GRUConv3d: fp16 HMMA GEMM (128x128 block, 32x64 warp, 3-stage cp.async,
// K-chunk 48, 2 CTAs/SM) + fp16 planes + dual-direction scan.
// ===========================================================================

#define NB 2
#define NSP 32768
#define NROW 65536
#define KDIM 864            // 32ci * 27taps = 18 * 48
#define MTOT 768

__device__ __align__(16) __half g_Bh[(size_t)NROW * KDIM];
__device__ __align__(16) __half g_Wh[(size_t)MTOT * KDIM];
__device__ __align__(16) __half g_Ch[(size_t)MTOT * NROW];
__device__ float                g_bias[MTOT];

// ---------------- helpers ---------------------------------------------------
__device__ __forceinline__ uint32_t smem_u32(const void* p) {
    uint32_t a;
    asm("{ .reg .u64 t; cvta.to.shared.u64 t, %1; cvt.u32.u64 %0, t; }" : "=r"(a) : "l"(p));
    return a;
}
__device__ __forceinline__ void cp16(uint32_t dst, const void* src) {
    asm volatile("cp.async.cg.shared.global [%0], [%1], 16;" :: "r"(dst), "l"(src));
}
#define CP_COMMIT() asm volatile("cp.async.commit_group;" ::: "memory")
#define CP_WAIT(n)  asm volatile("cp.async.wait_group %0;" :: "n"(n) : "memory")

#define LDSM4(r, a) \
    asm volatile("ldmatrix.sync.aligned.m8n8.x4.shared.b16 {%0,%1,%2,%3}, [%4];" \
                 : "=r"((r)[0]), "=r"((r)[1]), "=r"((r)[2]), "=r"((r)[3]) : "r"(a))

#define MMA16816(c, a, b0, b1) \
    asm volatile("mma.sync.aligned.m16n8k16.row.col.f32.f16.f16.f32 " \
                 "{%0,%1,%2,%3}, {%4,%5,%6,%7}, {%8,%9}, {%0,%1,%2,%3};" \
                 : "+f"((c)[0]), "+f"((c)[1]), "+f"((c)[2]), "+f"((c)[3]) \
                 : "r"((a)[0]), "r"((a)[1]), "r"((a)[2]), "r"((a)[3]), \
                   "r"(b0), "r"(b1))

// ---------------- 1) weight prep --------------------------------------------
__global__ void wprep_kernel(const float* __restrict__ Wh, const float* __restrict__ bh,
                             const float* __restrict__ Wz, const float* __restrict__ bz,
                             const float* __restrict__ Ws, const float* __restrict__ bs)
{
    const int m = blockIdx.x;
    const int n = m / 96, r = m % 96, g = r >> 5, co = r & 31;
    const float* Wp = (g == 0) ? Wh : ((g == 1) ? Wz : Ws);
    const float* bp = (g == 0) ? bh : ((g == 1) ? bz : bs);
    if (threadIdx.x == 0) g_bias[m] = bp[n * 32 + co];
    for (int k = threadIdx.x; k < KDIM; k += blockDim.x) {
        int ci = k / 27, t = k % 27;
        g_Wh[(size_t)m * KDIM + k] =
            __float2half(Wp[((n * 32 + co) * 32 + ci) * 27 + t]);
    }
}

// ---------------- 2) im2col --------------------------------------------------
#define I2C_STRIDE 904
#define I2C_SMEM (32 * I2C_STRIDE * 2)
__global__ void __launch_bounds__(256)
im2col_kernel(const float* __restrict__ x)
{
    extern __shared__ __half sm2[];
    const int tid = threadIdx.x, lane = tid & 31, wi = tid >> 5;
    const int bid = blockIdx.x;
    const int b = bid >> 10, d = (bid >> 5) & 31, h = bid & 31;

    for (int k = wi; k < KDIM; k += 8) {
        int ci = k / 27, t = k % 27;
        int td = t / 9, th = (t % 9) / 3, tw = t % 3;
        int gd = d + td - 1, gh = h + th - 1, gw = lane + tw - 1;
        float v = 0.f;
        if (gd >= 0 && gd < 32 && gh >= 0 && gh < 32 && gw >= 0 && gw < 32)
            v = x[(((b * 32 + ci) * 32 + gd) * 32 + gh) * 32 + gw];
        sm2[lane * I2C_STRIDE + k] = __float2half(v);
    }
    __syncthreads();

    const size_t row0 = (size_t)b * NSP + d * 1024 + h * 32;
    const uint4* smv = (const uint4*)sm2;
    uint4* gv = (uint4*)(g_Bh + row0 * KDIM);
    const int KV = KDIM / 8;
    for (int idx = tid; idx < 32 * KV; idx += 256) {
        int w = idx / KV, kv = idx % KV;
        gv[(size_t)w * KV + kv] = smv[w * (I2C_STRIDE / 8) + kv];
    }
}

// ---------------- 3) GEMM: 128x128 block, 32x64 warp, K-chunk 48, 3 stages ---
#define KCH 48
#define ASTR_B 112                          // 96B data, 112B stride (conflict-free)
#define REG_B_OFF 14336                     // 128 * 112
#define STAGE_B 28672
#define NSTG 3
#define GEMM_SMEM (NSTG * STAGE_B)          // 86016
#define NKC (KDIM / KCH)                    // 18

__global__ void __launch_bounds__(256, 2)
gemm_kernel()
{
    extern __shared__ __align__(16) char sm[];
    const int tid = threadIdx.x, lane = tid & 31, wid = tid >> 5;
    const int m0 = blockIdx.x * 128;
    const size_t n0 = (size_t)blockIdx.y * 128;
    const int wm = wid & 3, wn = wid >> 2;
    const uint32_t sbase = smem_u32(sm);

    const char* gA = (const char*)g_Wh + (size_t)m0 * (KDIM * 2);
    const char* gB = (const char*)g_Bh + n0 * (KDIM * 2);

    float acc[2][8][4];
#pragma unroll
    for (int i = 0; i < 2; ++i)
#pragma unroll
        for (int j = 0; j < 8; ++j)
#pragma unroll
            for (int q = 0; q < 4; ++q) acc[i][j][q] = 0.f;

    const int a_row = lane & 15;
    const int a_k8  = (lane >> 4) << 3;
    const int b_row = wn * 64 + (lane & 7) + ((lane >> 4) << 3);
    const int b_k8  = ((lane >> 3) & 1) << 3;

    auto load_stage = [&](int kc, int s) {
        const int koff = kc * (KCH * 2);              // 96 bytes per chunk
        const uint32_t st = sbase + s * STAGE_B;
        // A: 128 rows x 96B = 768 cp16; B same
        for (int i = tid; i < 768; i += 256) {
            int r = i / 6, c = (i % 6) << 4;
            uint32_t d = st + r * ASTR_B + c;
            size_t go = (size_t)r * (KDIM * 2) + koff + c;
            cp16(d, gA + go);
            cp16(d + REG_B_OFF, gB + go);
        }
        CP_COMMIT();
    };

    auto compute = [&](int s) {
        const uint32_t st = sbase + s * STAGE_B;
#pragma unroll
        for (int ks = 0; ks < 3; ++ks) {              // 3 x k16 per chunk
            uint32_t A[2][4], B[4][4];
#pragma unroll
            for (int mt2 = 0; mt2 < 2; ++mt2) {
                uint32_t a = st + (wm * 32 + mt2 * 16 + a_row) * ASTR_B
                               + (ks * 16 + a_k8) * 2;
                LDSM4(A[mt2], a);
            }
#pragma unroll
            for (int bt = 0; bt < 4; ++bt) {
                uint32_t a = st + REG_B_OFF + (b_row + bt * 16) * ASTR_B
                               + (ks * 16 + b_k8) * 2;
                LDSM4(B[bt], a);
            }
#pragma unroll
            for (int mt2 = 0; mt2 < 2; ++mt2)
#pragma unroll
                for (int nt8 = 0; nt8 < 8; ++nt8) {
                    const uint32_t* bb = &B[nt8 >> 1][(nt8 & 1) * 2];
                    MMA16816(acc[mt2][nt8], A[mt2], bb[0], bb[1]);
                }
        }
    };

    load_stage(0, 0);
    load_stage(1, 1);
    int s = 0;
    for (int kc = 0; kc < NKC; ++kc) {
        CP_WAIT(1);
        __syncthreads();
        if (kc + 2 < NKC) {
            int s2 = s + 2; if (s2 >= NSTG) s2 -= NSTG;
            load_stage(kc + 2, s2);
        }
        compute(s);
        if (++s == NSTG) s = 0;
    }

    // epilogue: bias + sigmoid for z/s gates, store fp16
    const int rgrp = lane >> 2, cpair = lane & 3;
#pragma unroll
    for (int mt2 = 0; mt2 < 2; ++mt2) {
        const int mA = m0 + wm * 32 + mt2 * 16 + rgrp;
        const bool gate = ((mA >> 5) % 3) != 0;
        const float biasA = g_bias[mA];
        const float biasB = g_bias[mA + 8];
#pragma unroll
        for (int nt8 = 0; nt8 < 8; ++nt8) {
            size_t col = n0 + wn * 64 + nt8 * 8 + cpair * 2;
            float v0 = acc[mt2][nt8][0] + biasA;
            float v1 = acc[mt2][nt8][1] + biasA;
            float v2 = acc[mt2][nt8][2] + biasB;
            float v3 = acc[mt2][nt8][3] + biasB;
            if (gate) {
                v0 = 1.f / (1.f + __expf(-v0));
                v1 = 1.f / (1.f + __expf(-v1));
                v2 = 1.f / (1.f + __expf(-v2));
                v3 = 1.f / (1.f + __expf(-v3));
            }
            *(__half2*)(g_Ch + (size_t)mA * NROW + col) =
                __floats2half2_rn(v0, v1);
            *(__half2*)(g_Ch + (size_t)(mA + 8) * NROW + col) =
                __floats2half2_rn(v2, v3);
        }
    }
}

// ---------------- 4) scan: 2 directions per thread (n, n+4) ------------------
__global__ void scan_kernel(const float* __restrict__ h0v)
{
    const int gwarp = (blockIdx.x * blockDim.x + threadIdx.x) >> 5;
    const int lane  = threadIdx.x & 31;
    const int n     = blockIdx.y;                 // 0..3 -> dirs n and n+4
    const int half  = gwarp & 1;
    const int d1i   = (gwarp >> 1) % 63;
    const int c     = (gwarp / 126) % 32;
    const int b     = gwarp / (126 * 32);
    if (b >= NB) return;

    const int delta1 = d1i - 31;
    const int delta2 = half * 32 + lane - 31;
    const bool lane_ok = (delta2 <= 31);

    // dir A = n (di=-1 since n<4), dir B = n+4 (di=+1); j,k dirs shared
    const int dj = (n & 2) ? 1 : -1;
    const int dk = (n & 1) ? 1 : -1;

    const int j0 = (dj > 0) ? -delta1 : 31 + delta1;
    const int k0 = (dk > 0) ? -delta2 : 31 + delta2;
    const int sjk = dj * 32 + dk;
    const int strideA = -1024 + sjk;              // di=-1
    const int strideB =  1024 + sjk;              // di=+1
    const int baseA = 31 * 1024 + j0 * 32 + k0;
    const int baseB =            j0 * 32 + k0;

    const int mlo = (delta1 > 0) ? delta1 : 0;
    const int mhi = (delta1 < 0) ? 31 + delta1 : 31;

    const size_t colb = (size_t)b * NSP;
    const int nA = n, nB = n + 4;
    __half* hbA      = g_Ch + (size_t)(nA * 96 +  0 + c) * NROW + colb;
    const __half* zA = g_Ch + (size_t)(nA * 96 + 32 + c) * NROW + colb;
    const __half* sA = g_Ch + (size_t)(nA * 96 + 64 + c) * NROW + colb;
    __half* hbB      = g_Ch + (size_t)(nB * 96 +  0 + c) * NROW + colb;
    const __half* zB = g_Ch + (size_t)(nB * 96 + 32 + c) * NROW + colb;
    const __half* sB = g_Ch + (size_t)(nB * 96 + 64 + c) * NROW + colb;

    float hA = h0v[nA * 32 + c];
    float hB = h0v[nB * 32 + c];

    int ia = baseA + mlo * strideA;
    int ib = baseB + mlo * strideB;
    bool act = lane_ok && ((unsigned)(mlo - delta2) <= 31u);
    float za = 0.f, ha = 0.f, sa = 0.f, zb = 0.f, hb = 0.f, sb = 0.f;
    if (act) {
        za = __half2float(zA[ia]); ha = __half2float(hbA[ia]); sa = __half2float(sA[ia]);
        zb = __half2float(zB[ib]); hb = __half2float(hbB[ib]); sb = __half2float(sB[ib]);
    }

    for (int m = mlo; m <= mhi; ++m) {
        const int na_ = ia + strideA, nb_ = ib + strideB;
        bool nact = (m != mhi) && lane_ok && ((unsigned)(m + 1 - delta2) <= 31u);
        float za1 = 0.f, ha1 = 0.f, sa1 = 0.f, zb1 = 0.f, hb1 = 0.f, sb1 = 0.f;
        if (nact) {
            za1 = __half2float(zA[na_]); ha1 = __half2float(hbA[na_]); sa1 = __half2float(sA[na_]);
            zb1 = __half2float(zB[nb_]); hb1 = __half2float(hbB[nb_]); sb1 = __half2float(sB[nb_]);
        }
        if (act) {
            hA = fmaf(za, ha - hA, hA);
            hB = fmaf(zb, hb - hB, hB);
            hbA[ia] = __float2half(hA * sa);
            hbB[ib] = __float2half(hB * sb);
        }
        ia = na_; ib = nb_; act = nact;
        za = za1; ha = ha1; sa = sa1; zb = zb1; hb = hb1; sb = sb1;
    }
}

// ---------------- 5) reduce (fp16 in, fp32 out) ------------------------------
__global__ void reduce_kernel(float* __restrict__ out)
{
    const int e4 = blockIdx.x * 256 + threadIdx.x;
    const int b = e4 >> 18;
    const int c = (e4 >> 13) & 31;
    const int sp4 = e4 & 8191;
    const size_t col = ((size_t)b * NSP + sp4 * 4);
    float2 a01 = make_float2(0.f, 0.f), a23 = make_float2(0.f, 0.f);
#pragma unroll
    for (int n = 0; n < 8; ++n) {
        const __half2* p = (const __half2*)(g_Ch + (size_t)(n * 96 + c) * NROW + col);
        float2 v0 = __half22float2(p[0]);
        float2 v1 = __half22float2(p[1]);
        a01.x += v0.x; a01.y += v0.y; a23.x += v1.x; a23.y += v1.y;
    }
    *(float4*)(out + (((size_t)b * 32 + c) * NSP + sp4 * 4)) =
        make_float4(a01.x, a01.y, a23.x, a23.y);
}

// ---------------- launch -------------------------------------------------------
extern "C" void kernel_launch(void* const* d_in, const int* in_sizes, int n_in,
                              void* d_out, int out_size)
{
    const float* x   = (const float*)d_in[0];
    const float* Wh  = (const float*)d_in[1];
    const float* bh  = (const float*)d_in[2];
    const float* Wz  = (const float*)d_in[3];
    const float* bz  = (const float*)d_in[4];
    const float* Ws  = (const float*)d_in[5];
    const float* bs  = (const float*)d_in[6];
    const float* h0v = (const float*)d_in[7];
    float* out = (float*)d_out;

    cudaFuncSetAttribute(im2col_kernel, cudaFuncAttributeMaxDynamicSharedMemorySize, I2C_SMEM);
    cudaFuncSetAttribute(gemm_kernel,   cudaFuncAttributeMaxDynamicSharedMemorySize, GEMM_SMEM);

    wprep_kernel<<<MTOT, 256>>>(Wh, bh, Wz, bz, Ws, bs);
    im2col_kernel<<<2048, 256, I2C_SMEM>>>(x);
    gemm_kernel<<<dim3(6, 512), 256, GEMM_SMEM>>>();
    scan_kernel<<<dim3(1008, 4), 256>>>(h0v);
    reduce_kernel<<<2048, 256>>>(out);
}

// round 11
// speedup vs baseline: 1.0451x; 1.0451x over previous
#include <cuda_runtime.h>
#include <cuda_fp16.h>
#include <cstdint>

// ===========================================================================
// GRUConv3d: fp16 HMMA GEMM (128x128 block, 32x64 warp, 4-stage cp.async,
// K-chunk 32, 2 CTAs/SM) + fp16 planes + scan with L2 prefetch.
// ===========================================================================

#define NB 2
#define NSP 32768
#define NROW 65536
#define KDIM 864
#define MTOT 768

__device__ __align__(16) __half g_Bh[(size_t)NROW * KDIM];
__device__ __align__(16) __half g_Wh[(size_t)MTOT * KDIM];
__device__ __align__(16) __half g_Ch[(size_t)MTOT * NROW];
__device__ float                g_bias[MTOT];

// ---------------- helpers ---------------------------------------------------
__device__ __forceinline__ uint32_t smem_u32(const void* p) {
    uint32_t a;
    asm("{ .reg .u64 t; cvta.to.shared.u64 t, %1; cvt.u32.u64 %0, t; }" : "=r"(a) : "l"(p));
    return a;
}
__device__ __forceinline__ void cp16(uint32_t dst, const void* src) {
    asm volatile("cp.async.cg.shared.global [%0], [%1], 16;" :: "r"(dst), "l"(src));
}
#define CP_COMMIT() asm volatile("cp.async.commit_group;" ::: "memory")
#define CP_WAIT(n)  asm volatile("cp.async.wait_group %0;" :: "n"(n) : "memory")
__device__ __forceinline__ void pfl2(const void* p) {
    asm volatile("prefetch.global.L2 [%0];" :: "l"(p));
}

#define LDSM4(r, a) \
    asm volatile("ldmatrix.sync.aligned.m8n8.x4.shared.b16 {%0,%1,%2,%3}, [%4];" \
                 : "=r"((r)[0]), "=r"((r)[1]), "=r"((r)[2]), "=r"((r)[3]) : "r"(a))

#define MMA16816(c, a, b0, b1) \
    asm volatile("mma.sync.aligned.m16n8k16.row.col.f32.f16.f16.f32 " \
                 "{%0,%1,%2,%3}, {%4,%5,%6,%7}, {%8,%9}, {%0,%1,%2,%3};" \
                 : "+f"((c)[0]), "+f"((c)[1]), "+f"((c)[2]), "+f"((c)[3]) \
                 : "r"((a)[0]), "r"((a)[1]), "r"((a)[2]), "r"((a)[3]), \
                   "r"(b0), "r"(b1))

// ---------------- 1) weight prep --------------------------------------------
__global__ void wprep_kernel(const float* __restrict__ Wh, const float* __restrict__ bh,
                             const float* __restrict__ Wz, const float* __restrict__ bz,
                             const float* __restrict__ Ws, const float* __restrict__ bs)
{
    const int m = blockIdx.x;
    const int n = m / 96, r = m % 96, g = r >> 5, co = r & 31;
    const float* Wp = (g == 0) ? Wh : ((g == 1) ? Wz : Ws);
    const float* bp = (g == 0) ? bh : ((g == 1) ? bz : bs);
    if (threadIdx.x == 0) g_bias[m] = bp[n * 32 + co];
    for (int k = threadIdx.x; k < KDIM; k += blockDim.x) {
        int ci = k / 27, t = k % 27;
        g_Wh[(size_t)m * KDIM + k] =
            __float2half(Wp[((n * 32 + co) * 32 + ci) * 27 + t]);
    }
}

// ---------------- 2) im2col --------------------------------------------------
#define I2C_STRIDE 904
#define I2C_SMEM (32 * I2C_STRIDE * 2)
__global__ void __launch_bounds__(256)
im2col_kernel(const float* __restrict__ x)
{
    extern __shared__ __half sm2[];
    const int tid = threadIdx.x, lane = tid & 31, wi = tid >> 5;
    const int bid = blockIdx.x;
    const int b = bid >> 10, d = (bid >> 5) & 31, h = bid & 31;

    for (int k = wi; k < KDIM; k += 8) {
        int ci = k / 27, t = k % 27;
        int td = t / 9, th = (t % 9) / 3, tw = t % 3;
        int gd = d + td - 1, gh = h + th - 1, gw = lane + tw - 1;
        float v = 0.f;
        if (gd >= 0 && gd < 32 && gh >= 0 && gh < 32 && gw >= 0 && gw < 32)
            v = x[(((b * 32 + ci) * 32 + gd) * 32 + gh) * 32 + gw];
        sm2[lane * I2C_STRIDE + k] = __float2half(v);
    }
    __syncthreads();

    const size_t row0 = (size_t)b * NSP + d * 1024 + h * 32;
    const uint4* smv = (const uint4*)sm2;
    uint4* gv = (uint4*)(g_Bh + row0 * KDIM);
    const int KV = KDIM / 8;
    for (int idx = tid; idx < 32 * KV; idx += 256) {
        int w = idx / KV, kv = idx % KV;
        gv[(size_t)w * KV + kv] = smv[w * (I2C_STRIDE / 8) + kv];
    }
}

// ---------------- 3) GEMM (HMMA fp16, 128x128 tile, 4-stage, K chunks of 32) -
#define ASTR_B 80
#define REG_B_OFF 10240
#define STAGE_B 20480
#define NSTG 4
#define GEMM_SMEM (NSTG * STAGE_B)          // 81920
#define NKC (KDIM / 32)                     // 27

__global__ void __launch_bounds__(256, 2)
gemm_kernel()
{
    extern __shared__ __align__(16) char sm[];
    const int tid = threadIdx.x, lane = tid & 31, wid = tid >> 5;
    const int m0 = blockIdx.x * 128;
    const size_t n0 = (size_t)blockIdx.y * 128;
    const int wm = wid & 3, wn = wid >> 2;
    const uint32_t sbase = smem_u32(sm);

    const char* gA = (const char*)g_Wh + (size_t)m0 * (KDIM * 2);
    const char* gB = (const char*)g_Bh + n0 * (KDIM * 2);

    float acc[2][8][4];
#pragma unroll
    for (int i = 0; i < 2; ++i)
#pragma unroll
        for (int j = 0; j < 8; ++j)
#pragma unroll
            for (int q = 0; q < 4; ++q) acc[i][j][q] = 0.f;

    const int a_row = lane & 15;
    const int a_k8  = (lane >> 4) << 3;
    const int b_row = wn * 64 + (lane & 7) + ((lane >> 4) << 3);
    const int b_k8  = ((lane >> 3) & 1) << 3;

    auto load_stage = [&](int kc, int s) {
        const int koff = kc * 64;
        const uint32_t st = sbase + s * STAGE_B;
        for (int i = tid; i < 512; i += 256) {
            int r = i >> 2, c = (i & 3) << 4;
            uint32_t d = st + r * ASTR_B + c;
            size_t go = (size_t)r * (KDIM * 2) + koff + c;
            cp16(d, gA + go);
            cp16(d + REG_B_OFF, gB + go);
        }
        CP_COMMIT();
    };

    auto compute = [&](int s) {
        const uint32_t st = sbase + s * STAGE_B;
#pragma unroll
        for (int ks = 0; ks < 2; ++ks) {
            uint32_t A[2][4], B[4][4];
#pragma unroll
            for (int mt2 = 0; mt2 < 2; ++mt2) {
                uint32_t a = st + (wm * 32 + mt2 * 16 + a_row) * ASTR_B
                               + (ks * 16 + a_k8) * 2;
                LDSM4(A[mt2], a);
            }
#pragma unroll
            for (int bt = 0; bt < 4; ++bt) {
                uint32_t a = st + REG_B_OFF + (b_row + bt * 16) * ASTR_B
                               + (ks * 16 + b_k8) * 2;
                LDSM4(B[bt], a);
            }
#pragma unroll
            for (int mt2 = 0; mt2 < 2; ++mt2)
#pragma unroll
                for (int nt8 = 0; nt8 < 8; ++nt8) {
                    const uint32_t* bb = &B[nt8 >> 1][(nt8 & 1) * 2];
                    MMA16816(acc[mt2][nt8], A[mt2], bb[0], bb[1]);
                }
        }
    };

    load_stage(0, 0);
    load_stage(1, 1);
    load_stage(2, 2);
    int s = 0;
    for (int kc = 0; kc < NKC; ++kc) {
        CP_WAIT(2);
        __syncthreads();
        if (kc + 3 < NKC) {
            int s3 = s + 3; if (s3 >= NSTG) s3 -= NSTG;
            load_stage(kc + 3, s3);
        }
        compute(s);
        if (++s == NSTG) s = 0;
    }

    // epilogue: bias + sigmoid for z/s gates, store fp16
    const int rgrp = lane >> 2, cpair = lane & 3;
#pragma unroll
    for (int mt2 = 0; mt2 < 2; ++mt2) {
        const int mA = m0 + wm * 32 + mt2 * 16 + rgrp;
        const bool gate = ((mA >> 5) % 3) != 0;
        const float biasA = g_bias[mA];
        const float biasB = g_bias[mA + 8];
#pragma unroll
        for (int nt8 = 0; nt8 < 8; ++nt8) {
            size_t col = n0 + wn * 64 + nt8 * 8 + cpair * 2;
            float v0 = acc[mt2][nt8][0] + biasA;
            float v1 = acc[mt2][nt8][1] + biasA;
            float v2 = acc[mt2][nt8][2] + biasB;
            float v3 = acc[mt2][nt8][3] + biasB;
            if (gate) {
                v0 = 1.f / (1.f + __expf(-v0));
                v1 = 1.f / (1.f + __expf(-v1));
                v2 = 1.f / (1.f + __expf(-v2));
                v3 = 1.f / (1.f + __expf(-v3));
            }
            *(__half2*)(g_Ch + (size_t)mA * NROW + col) =
                __floats2half2_rn(v0, v1);
            *(__half2*)(g_Ch + (size_t)(mA + 8) * NROW + col) =
                __floats2half2_rn(v2, v3);
        }
    }
}

// ---------------- 4) scan (dist-1 pipeline + L2 prefetch 2 ahead) ------------
__global__ void scan_kernel(const float* __restrict__ h0v)
{
    const int gwarp = (blockIdx.x * blockDim.x + threadIdx.x) >> 5;
    const int lane  = threadIdx.x & 31;
    const int n     = blockIdx.y;
    const int half  = gwarp & 1;
    const int d1i   = (gwarp >> 1) % 63;
    const int c     = (gwarp / 126) % 32;
    const int b     = gwarp / (126 * 32);
    if (b >= NB) return;

    const int delta1 = d1i - 31;
    const int delta2 = half * 32 + lane - 31;
    const bool lane_ok = (delta2 <= 31);

    const int di = (n & 4) ? 1 : -1;
    const int dj = (n & 2) ? 1 : -1;
    const int dk = (n & 1) ? 1 : -1;

    const int stride = di * 1024 + dj * 32 + dk;
    const int i0 = (di > 0) ? 0 : 31;
    const int j0 = (dj > 0) ? -delta1 : 31 + delta1;
    const int k0 = (dk > 0) ? -delta2 : 31 + delta2;
    const int base = i0 * 1024 + j0 * 32 + k0;

    const int mlo = (delta1 > 0) ? delta1 : 0;
    const int mhi = (delta1 < 0) ? 31 + delta1 : 31;

    const size_t colb = (size_t)b * NSP;
    __half* hbp       = g_Ch + (size_t)(n * 96 +  0 + c) * NROW + colb;
    const __half* zp  = g_Ch + (size_t)(n * 96 + 32 + c) * NROW + colb;
    const __half* sp  = g_Ch + (size_t)(n * 96 + 64 + c) * NROW + colb;

    float h = h0v[n * 32 + c];

    int idx = base + mlo * stride;
    bool act = lane_ok && ((unsigned)(mlo - delta2) <= 31u);
    float z = 0.f, hb = 0.f, s = 0.f;
    if (act) { z = __half2float(zp[idx]); hb = __half2float(hbp[idx]); s = __half2float(sp[idx]); }
    // warm L2 for step mlo+1
    {
        const int p1 = idx + stride;
        if (lane_ok && ((unsigned)(mlo + 1 - delta2) <= 31u) && mlo + 1 <= mhi) {
            pfl2(zp + p1); pfl2(hbp + p1); pfl2(sp + p1);
        }
    }

    for (int m = mlo; m <= mhi; ++m) {
        const int nidx = idx + stride;
        const bool last = (m == mhi);
        bool nact = !last && lane_ok && ((unsigned)(m + 1 - delta2) <= 31u);

        // prefetch step m+2 into L2 (register-free latency reduction)
        {
            const int p2 = nidx + stride;
            bool pact = (m + 2 <= mhi) && lane_ok && ((unsigned)(m + 2 - delta2) <= 31u);
            if (pact) { pfl2(zp + p2); pfl2(hbp + p2); pfl2(sp + p2); }
        }

        float nz = 0.f, nhb = 0.f, ns = 0.f;
        if (nact) { nz = __half2float(zp[nidx]); nhb = __half2float(hbp[nidx]); ns = __half2float(sp[nidx]); }

        if (act) {
            h = fmaf(z, hb - h, h);
            hbp[idx] = __float2half(h * s);
        }
        idx = nidx; act = nact; z = nz; hb = nhb; s = ns;
    }
}

// ---------------- 5) reduce (fp16 in, fp32 out) ------------------------------
__global__ void reduce_kernel(float* __restrict__ out)
{
    const int e4 = blockIdx.x * 256 + threadIdx.x;
    const int b = e4 >> 18;
    const int c = (e4 >> 13) & 31;
    const int sp4 = e4 & 8191;
    const size_t col = ((size_t)b * NSP + sp4 * 4);
    float2 a01 = make_float2(0.f, 0.f), a23 = make_float2(0.f, 0.f);
#pragma unroll
    for (int n = 0; n < 8; ++n) {
        const __half2* p = (const __half2*)(g_Ch + (size_t)(n * 96 + c) * NROW + col);
        float2 v0 = __half22float2(p[0]);
        float2 v1 = __half22float2(p[1]);
        a01.x += v0.x; a01.y += v0.y; a23.x += v1.x; a23.y += v1.y;
    }
    *(float4*)(out + (((size_t)b * 32 + c) * NSP + sp4 * 4)) =
        make_float4(a01.x, a01.y, a23.x, a23.y);
}

// ---------------- launch -------------------------------------------------------
extern "C" void kernel_launch(void* const* d_in, const int* in_sizes, int n_in,
                              void* d_out, int out_size)
{
    const float* x   = (const float*)d_in[0];
    const float* Wh  = (const float*)d_in[1];
    const float* bh  = (const float*)d_in[2];
    const float* Wz  = (const float*)d_in[3];
    const float* bz  = (const float*)d_in[4];
    const float* Ws  = (const float*)d_in[5];
    const float* bs  = (const float*)d_in[6];
    const float* h0v = (const float*)d_in[7];
    float* out = (float*)d_out;

    cudaFuncSetAttribute(im2col_kernel, cudaFuncAttributeMaxDynamicSharedMemorySize, I2C_SMEM);
    cudaFuncSetAttribute(gemm_kernel,   cudaFuncAttributeMaxDynamicSharedMemorySize, GEMM_SMEM);

    wprep_kernel<<<MTOT, 256>>>(Wh, bh, Wz, bz, Ws, bs);
    im2col_kernel<<<2048, 256, I2C_SMEM>>>(x);
    gemm_kernel<<<dim3(6, 512), 256, GEMM_SMEM>>>();
    scan_kernel<<<dim3(1008, 8), 256>>>(h0v);
    reduce_kernel<<<2048, 256>>>(out);
}

// round 13
// speedup vs baseline: 1.4400x; 1.3779x over previous
#include <cuda_runtime.h>
#include <cuda_fp16.h>
#include <cstdint>

// ===========================================================================
// GRUConv3d: implicit-im2col fp16 HMMA GEMM.
//  - x transposed once to channels-last fp16 x_t[b][d][h][w][ci] (8 MB)
//  - K ordered tap-major (k = tap*32 + ci): one K-chunk = one tap, so the
//    GEMM B-tile loader gathers 64B/voxel directly from x_t with cp.async
//    zero-fill for halo -> no im2col pass, B reads are L2-resident.
//  - scan: 8 dirs, affine diagonal chains, dist-1 register pipeline.
// ===========================================================================

#define NB 2
#define NSP 32768
#define NROW 65536
#define KDIM 864            // 27 taps * 32 ci
#define MTOT 768

__device__ __align__(16) __half g_Xt[(size_t)NB * NSP * 32];   // 8 MB
__device__ __align__(16) __half g_Wh[(size_t)MTOT * KDIM];
__device__ __align__(16) __half g_Ch[(size_t)MTOT * NROW];
__device__ float                g_bias[MTOT];

// ---------------- helpers ---------------------------------------------------
__device__ __forceinline__ uint32_t smem_u32(const void* p) {
    uint32_t a;
    asm("{ .reg .u64 t; cvta.to.shared.u64 t, %1; cvt.u32.u64 %0, t; }" : "=r"(a) : "l"(p));
    return a;
}
__device__ __forceinline__ void cp16(uint32_t dst, const void* src) {
    asm volatile("cp.async.cg.shared.global [%0], [%1], 16;" :: "r"(dst), "l"(src));
}
__device__ __forceinline__ void cp16z(uint32_t dst, const void* src, uint32_t sz) {
    asm volatile("cp.async.cg.shared.global [%0], [%1], 16, %2;"
                 :: "r"(dst), "l"(src), "r"(sz));
}
#define CP_COMMIT() asm volatile("cp.async.commit_group;" ::: "memory")
#define CP_WAIT(n)  asm volatile("cp.async.wait_group %0;" :: "n"(n) : "memory")

#define LDSM4(r, a) \
    asm volatile("ldmatrix.sync.aligned.m8n8.x4.shared.b16 {%0,%1,%2,%3}, [%4];" \
                 : "=r"((r)[0]), "=r"((r)[1]), "=r"((r)[2]), "=r"((r)[3]) : "r"(a))

#define MMA16816(c, a, b0, b1) \
    asm volatile("mma.sync.aligned.m16n8k16.row.col.f32.f16.f16.f32 " \
                 "{%0,%1,%2,%3}, {%4,%5,%6,%7}, {%8,%9}, {%0,%1,%2,%3};" \
                 : "+f"((c)[0]), "+f"((c)[1]), "+f"((c)[2]), "+f"((c)[3]) \
                 : "r"((a)[0]), "r"((a)[1]), "r"((a)[2]), "r"((a)[3]), \
                   "r"(b0), "r"(b1))

// ---------------- 1) weight prep (tap-major K) -------------------------------
__global__ void wprep_kernel(const float* __restrict__ Wh, const float* __restrict__ bh,
                             const float* __restrict__ Wz, const float* __restrict__ bz,
                             const float* __restrict__ Ws, const float* __restrict__ bs)
{
    const int m = blockIdx.x;
    const int n = m / 96, r = m % 96, g = r >> 5, co = r & 31;
    const float* Wp = (g == 0) ? Wh : ((g == 1) ? Wz : Ws);
    const float* bp = (g == 0) ? bh : ((g == 1) ? bz : bs);
    if (threadIdx.x == 0) g_bias[m] = bp[n * 32 + co];
    for (int k = threadIdx.x; k < KDIM; k += blockDim.x) {
        int t = k >> 5, ci = k & 31;                 // tap-major
        g_Wh[(size_t)m * KDIM + k] =
            __float2half(Wp[((n * 32 + co) * 32 + ci) * 27 + t]);
    }
}

// ---------------- 2) x transpose to channels-last fp16 -----------------------
__global__ void xprep_kernel(const float* __restrict__ x)
{
    __shared__ float tile[32][33];
    const int bid = blockIdx.x;                      // (b,d,h)
    const int b = bid >> 10, d = (bid >> 5) & 31, h = bid & 31;
    const int tid = threadIdx.x;
    for (int i = tid; i < 1024; i += 256) {
        int ci = i >> 5, w = i & 31;
        tile[ci][w] = x[(((b * 32 + ci) * 32 + d) * 32 + h) * 32 + w];
    }
    __syncthreads();
    __half* dst = g_Xt + ((size_t)(b * NSP) + d * 1024 + h * 32) * 32;
    for (int i = tid; i < 1024; i += 256) {
        int w = i >> 5, ci = i & 31;
        dst[w * 32 + ci] = __float2half(tile[ci][w]);
    }
}

// ---------------- 3) GEMM (implicit im2col, 128x128, 3-stage, K-chunk=tap) ---
#define ASTR_B 80
#define REG_B_OFF 10240
#define STAGE_B 20480
#define NSTG 3
#define GEMM_SMEM (NSTG * STAGE_B)
#define NKC 27

__global__ void __launch_bounds__(256, 2)
gemm_kernel()
{
    extern __shared__ __align__(16) char sm[];
    const int tid = threadIdx.x, lane = tid & 31, wid = tid >> 5;
    const int m0 = blockIdx.x * 128;
    const int nt = blockIdx.y;                       // 512 tiles of 128 rows
    const int b  = nt >> 8;                          // 256 tiles per batch
    const int d  = (nt >> 3) & 31;
    const int h0 = (nt & 7) * 4;
    const size_t n0 = (size_t)nt * 128;
    const int wm = wid & 3, wn = wid >> 2;
    const uint32_t sbase = smem_u32(sm);

    const char* gA = (const char*)g_Wh + (size_t)m0 * (KDIM * 2);
    const char* xb = (const char*)g_Xt + (size_t)b * NSP * 64;

    float acc[2][8][4];
#pragma unroll
    for (int i = 0; i < 2; ++i)
#pragma unroll
        for (int j = 0; j < 8; ++j)
#pragma unroll
            for (int q = 0; q < 4; ++q) acc[i][j][q] = 0.f;

    const int a_row = lane & 15;
    const int a_k8  = (lane >> 4) << 3;
    const int b_row = wn * 64 + (lane & 7) + ((lane >> 4) << 3);
    const int b_k8  = ((lane >> 3) & 1) << 3;

    auto load_stage = [&](int kc, int s) {
        const uint32_t st = sbase + s * STAGE_B;
        // A: 128 rows x 64B
        for (int i = tid; i < 512; i += 256) {
            int r = i >> 2, c = (i & 3) << 4;
            cp16(st + r * ASTR_B + c, gA + (size_t)r * (KDIM * 2) + kc * 64 + c);
        }
        // B: implicit im2col gather from x_t; one tap per chunk
        const int td = kc / 9, t9 = kc % 9;
        const int th = t9 / 3, tw = t9 % 3;
        const int dd = d + td - 1;
        const bool dok = (unsigned)dd < 32u;
        for (int i = tid; i < 512; i += 256) {
            int r = i >> 2, c = (i & 3) << 4;
            int hh = h0 + (r >> 5) + th - 1;
            int ww = (r & 31) + tw - 1;
            bool valid = dok && (unsigned)hh < 32u && (unsigned)ww < 32u;
            const char* src = xb + ((size_t)(dd * 1024 + hh * 32 + ww)) * 64 + c;
            cp16z(st + REG_B_OFF + r * ASTR_B + c, src, valid ? 16u : 0u);
        }
        CP_COMMIT();
    };

    auto compute = [&](int s) {
        const uint32_t st = sbase + s * STAGE_B;
#pragma unroll
        for (int ks = 0; ks < 2; ++ks) {
            uint32_t A[2][4], B[4][4];
#pragma unroll
            for (int mt2 = 0; mt2 < 2; ++mt2) {
                uint32_t a = st + (wm * 32 + mt2 * 16 + a_row) * ASTR_B
                               + (ks * 16 + a_k8) * 2;
                LDSM4(A[mt2], a);
            }
#pragma unroll
            for (int bt = 0; bt < 4; ++bt) {
                uint32_t a = st + REG_B_OFF + (b_row + bt * 16) * ASTR_B
                               + (ks * 16 + b_k8) * 2;
                LDSM4(B[bt], a);
            }
#pragma unroll
            for (int mt2 = 0; mt2 < 2; ++mt2)
#pragma unroll
                for (int nt8 = 0; nt8 < 8; ++nt8) {
                    const uint32_t* bb = &B[nt8 >> 1][(nt8 & 1) * 2];
                    MMA16816(acc[mt2][nt8], A[mt2], bb[0], bb[1]);
                }
        }
    };

    load_stage(0, 0);
    load_stage(1, 1);
    int s = 0;
    for (int kc = 0; kc < NKC; ++kc) {
        CP_WAIT(1);
        __syncthreads();
        if (kc + 2 < NKC) {
            int s2 = s + 2; if (s2 >= NSTG) s2 -= NSTG;
            load_stage(kc + 2, s2);
        }
        compute(s);
        if (++s == NSTG) s = 0;
    }

    // epilogue: bias + sigmoid for z/s gates, store fp16
    const int rgrp = lane >> 2, cpair = lane & 3;
#pragma unroll
    for (int mt2 = 0; mt2 < 2; ++mt2) {
        const int mA = m0 + wm * 32 + mt2 * 16 + rgrp;
        const bool gate = ((mA >> 5) % 3) != 0;
        const float biasA = g_bias[mA];
        const float biasB = g_bias[mA + 8];
#pragma unroll
        for (int nt8 = 0; nt8 < 8; ++nt8) {
            size_t col = n0 + wn * 64 + nt8 * 8 + cpair * 2;
            float v0 = acc[mt2][nt8][0] + biasA;
            float v1 = acc[mt2][nt8][1] + biasA;
            float v2 = acc[mt2][nt8][2] + biasB;
            float v3 = acc[mt2][nt8][3] + biasB;
            if (gate) {
                v0 = 1.f / (1.f + __expf(-v0));
                v1 = 1.f / (1.f + __expf(-v1));
                v2 = 1.f / (1.f + __expf(-v2));
                v3 = 1.f / (1.f + __expf(-v3));
            }
            *(__half2*)(g_Ch + (size_t)mA * NROW + col) =
                __floats2half2_rn(v0, v1);
            *(__half2*)(g_Ch + (size_t)(mA + 8) * NROW + col) =
                __floats2half2_rn(v2, v3);
        }
    }
}

// ---------------- 4) scan (dist-1 register pipeline) -------------------------
__global__ void scan_kernel(const float* __restrict__ h0v)
{
    const int gwarp = (blockIdx.x * blockDim.x + threadIdx.x) >> 5;
    const int lane  = threadIdx.x & 31;
    const int n     = blockIdx.y;
    const int half  = gwarp & 1;
    const int d1i   = (gwarp >> 1) % 63;
    const int c     = (gwarp / 126) % 32;
    const int b     = gwarp / (126 * 32);
    if (b >= NB) return;

    const int delta1 = d1i - 31;
    const int delta2 = half * 32 + lane - 31;
    const bool lane_ok = (delta2 <= 31);

    const int di = (n & 4) ? 1 : -1;
    const int dj = (n & 2) ? 1 : -1;
    const int dk = (n & 1) ? 1 : -1;

    const int stride = di * 1024 + dj * 32 + dk;
    const int i0 = (di > 0) ? 0 : 31;
    const int j0 = (dj > 0) ? -delta1 : 31 + delta1;
    const int k0 = (dk > 0) ? -delta2 : 31 + delta2;
    const int base = i0 * 1024 + j0 * 32 + k0;

    const int mlo = (delta1 > 0) ? delta1 : 0;
    const int mhi = (delta1 < 0) ? 31 + delta1 : 31;

    const size_t colb = (size_t)b * NSP;
    __half* hbp       = g_Ch + (size_t)(n * 96 +  0 + c) * NROW + colb;
    const __half* zp  = g_Ch + (size_t)(n * 96 + 32 + c) * NROW + colb;
    const __half* sp  = g_Ch + (size_t)(n * 96 + 64 + c) * NROW + colb;

    float h = h0v[n * 32 + c];

    int idx = base + mlo * stride;
    bool act = lane_ok && ((unsigned)(mlo - delta2) <= 31u);
    float z = 0.f, hb = 0.f, s = 0.f;
    if (act) { z = __half2float(zp[idx]); hb = __half2float(hbp[idx]); s = __half2float(sp[idx]); }

    for (int m = mlo; m <= mhi; ++m) {
        const int nidx = idx + stride;
        const bool last = (m == mhi);
        bool nact = !last && lane_ok && ((unsigned)(m + 1 - delta2) <= 31u);
        float nz = 0.f, nhb = 0.f, ns = 0.f;
        if (nact) { nz = __half2float(zp[nidx]); nhb = __half2float(hbp[nidx]); ns = __half2float(sp[nidx]); }

        if (act) {
            h = fmaf(z, hb - h, h);
            hbp[idx] = __float2half(h * s);
        }
        idx = nidx; act = nact; z = nz; hb = nhb; s = ns;
    }
}

// ---------------- 5) reduce (fp16 in, fp32 out) ------------------------------
__global__ void reduce_kernel(float* __restrict__ out)
{
    const int e4 = blockIdx.x * 256 + threadIdx.x;
    const int b = e4 >> 18;
    const int c = (e4 >> 13) & 31;
    const int sp4 = e4 & 8191;
    const size_t col = ((size_t)b * NSP + sp4 * 4);
    float2 a01 = make_float2(0.f, 0.f), a23 = make_float2(0.f, 0.f);
#pragma unroll
    for (int n = 0; n < 8; ++n) {
        const __half2* p = (const __half2*)(g_Ch + (size_t)(n * 96 + c) * NROW + col);
        float2 v0 = __half22float2(p[0]);
        float2 v1 = __half22float2(p[1]);
        a01.x += v0.x; a01.y += v0.y; a23.x += v1.x; a23.y += v1.y;
    }
    *(float4*)(out + (((size_t)b * 32 + c) * NSP + sp4 * 4)) =
        make_float4(a01.x, a01.y, a23.x, a23.y);
}

// ---------------- launch -------------------------------------------------------
extern "C" void kernel_launch(void* const* d_in, const int* in_sizes, int n_in,
                              void* d_out, int out_size)
{
    const float* x   = (const float*)d_in[0];
    const float* Wh  = (const float*)d_in[1];
    const float* bh  = (const float*)d_in[2];
    const float* Wz  = (const float*)d_in[3];
    const float* bz  = (const float*)d_in[4];
    const float* Ws  = (const float*)d_in[5];
    const float* bs  = (const float*)d_in[6];
    const float* h0v = (const float*)d_in[7];
    float* out = (float*)d_out;

    cudaFuncSetAttribute(gemm_kernel, cudaFuncAttributeMaxDynamicSharedMemorySize, GEMM_SMEM);

    wprep_kernel<<<MTOT, 256>>>(Wh, bh, Wz, bz, Ws, bs);
    xprep_kernel<<<2048, 256>>>(x);
    gemm_kernel<<<dim3(6, 512), 256, GEMM_SMEM>>>();
    scan_kernel<<<dim3(1008, 8), 256>>>(h0v);
    reduce_kernel<<<2048, 256>>>(out);
}

// round 14
// speedup vs baseline: 1.5353x; 1.0662x over previous
#include <cuda_runtime.h>
#include <cuda_fp16.h>
#include <cstdint>

// ===========================================================================
// GRUConv3d: implicit-im2col fp16 HMMA GEMM (unchanged from R11 best) +
// wavefront slab scan: block = (b,c,dir), 1024 threads = (j,k) grid, 32 steps
// over i with diagonal neighbor via double-buffered 33x33 smem tile.
// ===========================================================================

#define NB 2
#define NSP 32768
#define NROW 65536
#define KDIM 864            // 27 taps * 32 ci
#define MTOT 768

__device__ __align__(16) __half g_Xt[(size_t)NB * NSP * 32];   // 8 MB
__device__ __align__(16) __half g_Wh[(size_t)MTOT * KDIM];
__device__ __align__(16) __half g_Ch[(size_t)MTOT * NROW];
__device__ float                g_bias[MTOT];

// ---------------- helpers ---------------------------------------------------
__device__ __forceinline__ uint32_t smem_u32(const void* p) {
    uint32_t a;
    asm("{ .reg .u64 t; cvta.to.shared.u64 t, %1; cvt.u32.u64 %0, t; }" : "=r"(a) : "l"(p));
    return a;
}
__device__ __forceinline__ void cp16(uint32_t dst, const void* src) {
    asm volatile("cp.async.cg.shared.global [%0], [%1], 16;" :: "r"(dst), "l"(src));
}
__device__ __forceinline__ void cp16z(uint32_t dst, const void* src, uint32_t sz) {
    asm volatile("cp.async.cg.shared.global [%0], [%1], 16, %2;"
                 :: "r"(dst), "l"(src), "r"(sz));
}
#define CP_COMMIT() asm volatile("cp.async.commit_group;" ::: "memory")
#define CP_WAIT(n)  asm volatile("cp.async.wait_group %0;" :: "n"(n) : "memory")

#define LDSM4(r, a) \
    asm volatile("ldmatrix.sync.aligned.m8n8.x4.shared.b16 {%0,%1,%2,%3}, [%4];" \
                 : "=r"((r)[0]), "=r"((r)[1]), "=r"((r)[2]), "=r"((r)[3]) : "r"(a))

#define MMA16816(c, a, b0, b1) \
    asm volatile("mma.sync.aligned.m16n8k16.row.col.f32.f16.f16.f32 " \
                 "{%0,%1,%2,%3}, {%4,%5,%6,%7}, {%8,%9}, {%0,%1,%2,%3};" \
                 : "+f"((c)[0]), "+f"((c)[1]), "+f"((c)[2]), "+f"((c)[3]) \
                 : "r"((a)[0]), "r"((a)[1]), "r"((a)[2]), "r"((a)[3]), \
                   "r"(b0), "r"(b1))

// ---------------- 1) weight prep (tap-major K) -------------------------------
__global__ void wprep_kernel(const float* __restrict__ Wh, const float* __restrict__ bh,
                             const float* __restrict__ Wz, const float* __restrict__ bz,
                             const float* __restrict__ Ws, const float* __restrict__ bs)
{
    const int m = blockIdx.x;
    const int n = m / 96, r = m % 96, g = r >> 5, co = r & 31;
    const float* Wp = (g == 0) ? Wh : ((g == 1) ? Wz : Ws);
    const float* bp = (g == 0) ? bh : ((g == 1) ? bz : bs);
    if (threadIdx.x == 0) g_bias[m] = bp[n * 32 + co];
    for (int k = threadIdx.x; k < KDIM; k += blockDim.x) {
        int t = k >> 5, ci = k & 31;
        g_Wh[(size_t)m * KDIM + k] =
            __float2half(Wp[((n * 32 + co) * 32 + ci) * 27 + t]);
    }
}

// ---------------- 2) x transpose to channels-last fp16 -----------------------
__global__ void xprep_kernel(const float* __restrict__ x)
{
    __shared__ float tile[32][33];
    const int bid = blockIdx.x;
    const int b = bid >> 10, d = (bid >> 5) & 31, h = bid & 31;
    const int tid = threadIdx.x;
    for (int i = tid; i < 1024; i += 256) {
        int ci = i >> 5, w = i & 31;
        tile[ci][w] = x[(((b * 32 + ci) * 32 + d) * 32 + h) * 32 + w];
    }
    __syncthreads();
    __half* dst = g_Xt + ((size_t)(b * NSP) + d * 1024 + h * 32) * 32;
    for (int i = tid; i < 1024; i += 256) {
        int w = i >> 5, ci = i & 31;
        dst[w * 32 + ci] = __float2half(tile[ci][w]);
    }
}

// ---------------- 3) GEMM (implicit im2col, 128x128, 3-stage, K-chunk=tap) ---
#define ASTR_B 80
#define REG_B_OFF 10240
#define STAGE_B 20480
#define NSTG 3
#define GEMM_SMEM (NSTG * STAGE_B)
#define NKC 27

__global__ void __launch_bounds__(256, 2)
gemm_kernel()
{
    extern __shared__ __align__(16) char sm[];
    const int tid = threadIdx.x, lane = tid & 31, wid = tid >> 5;
    const int m0 = blockIdx.x * 128;
    const int nt = blockIdx.y;
    const int b  = nt >> 8;
    const int d  = (nt >> 3) & 31;
    const int h0 = (nt & 7) * 4;
    const size_t n0 = (size_t)nt * 128;
    const int wm = wid & 3, wn = wid >> 2;
    const uint32_t sbase = smem_u32(sm);

    const char* gA = (const char*)g_Wh + (size_t)m0 * (KDIM * 2);
    const char* xb = (const char*)g_Xt + (size_t)b * NSP * 64;

    float acc[2][8][4];
#pragma unroll
    for (int i = 0; i < 2; ++i)
#pragma unroll
        for (int j = 0; j < 8; ++j)
#pragma unroll
            for (int q = 0; q < 4; ++q) acc[i][j][q] = 0.f;

    const int a_row = lane & 15;
    const int a_k8  = (lane >> 4) << 3;
    const int b_row = wn * 64 + (lane & 7) + ((lane >> 4) << 3);
    const int b_k8  = ((lane >> 3) & 1) << 3;

    auto load_stage = [&](int kc, int s) {
        const uint32_t st = sbase + s * STAGE_B;
        for (int i = tid; i < 512; i += 256) {
            int r = i >> 2, c = (i & 3) << 4;
            cp16(st + r * ASTR_B + c, gA + (size_t)r * (KDIM * 2) + kc * 64 + c);
        }
        const int td = kc / 9, t9 = kc % 9;
        const int th = t9 / 3, tw = t9 % 3;
        const int dd = d + td - 1;
        const bool dok = (unsigned)dd < 32u;
        for (int i = tid; i < 512; i += 256) {
            int r = i >> 2, c = (i & 3) << 4;
            int hh = h0 + (r >> 5) + th - 1;
            int ww = (r & 31) + tw - 1;
            bool valid = dok && (unsigned)hh < 32u && (unsigned)ww < 32u;
            const char* src = xb + ((size_t)(dd * 1024 + hh * 32 + ww)) * 64 + c;
            cp16z(st + REG_B_OFF + r * ASTR_B + c, src, valid ? 16u : 0u);
        }
        CP_COMMIT();
    };

    auto compute = [&](int s) {
        const uint32_t st = sbase + s * STAGE_B;
#pragma unroll
        for (int ks = 0; ks < 2; ++ks) {
            uint32_t A[2][4], B[4][4];
#pragma unroll
            for (int mt2 = 0; mt2 < 2; ++mt2) {
                uint32_t a = st + (wm * 32 + mt2 * 16 + a_row) * ASTR_B
                               + (ks * 16 + a_k8) * 2;
                LDSM4(A[mt2], a);
            }
#pragma unroll
            for (int bt = 0; bt < 4; ++bt) {
                uint32_t a = st + REG_B_OFF + (b_row + bt * 16) * ASTR_B
                               + (ks * 16 + b_k8) * 2;
                LDSM4(B[bt], a);
            }
#pragma unroll
            for (int mt2 = 0; mt2 < 2; ++mt2)
#pragma unroll
                for (int nt8 = 0; nt8 < 8; ++nt8) {
                    const uint32_t* bb = &B[nt8 >> 1][(nt8 & 1) * 2];
                    MMA16816(acc[mt2][nt8], A[mt2], bb[0], bb[1]);
                }
        }
    };

    load_stage(0, 0);
    load_stage(1, 1);
    int s = 0;
    for (int kc = 0; kc < NKC; ++kc) {
        CP_WAIT(1);
        __syncthreads();
        if (kc + 2 < NKC) {
            int s2 = s + 2; if (s2 >= NSTG) s2 -= NSTG;
            load_stage(kc + 2, s2);
        }
        compute(s);
        if (++s == NSTG) s = 0;
    }

    const int rgrp = lane >> 2, cpair = lane & 3;
#pragma unroll
    for (int mt2 = 0; mt2 < 2; ++mt2) {
        const int mA = m0 + wm * 32 + mt2 * 16 + rgrp;
        const bool gate = ((mA >> 5) % 3) != 0;
        const float biasA = g_bias[mA];
        const float biasB = g_bias[mA + 8];
#pragma unroll
        for (int nt8 = 0; nt8 < 8; ++nt8) {
            size_t col = n0 + wn * 64 + nt8 * 8 + cpair * 2;
            float v0 = acc[mt2][nt8][0] + biasA;
            float v1 = acc[mt2][nt8][1] + biasA;
            float v2 = acc[mt2][nt8][2] + biasB;
            float v3 = acc[mt2][nt8][3] + biasB;
            if (gate) {
                v0 = 1.f / (1.f + __expf(-v0));
                v1 = 1.f / (1.f + __expf(-v1));
                v2 = 1.f / (1.f + __expf(-v2));
                v3 = 1.f / (1.f + __expf(-v3));
            }
            *(__half2*)(g_Ch + (size_t)mA * NROW + col) =
                __floats2half2_rn(v0, v1);
            *(__half2*)(g_Ch + (size_t)(mA + 8) * NROW + col) =
                __floats2half2_rn(v2, v3);
        }
    }
}

// ---------------- 4) scan: wavefront slabs, 1 block per (b,c,dir) ------------
// Thread (j,k) in flipped frame; physical coords fixed per thread except i.
// O[i,j,k] = z*hb + (1-z)*prev, prev = h0 if min(i,j,k)==0 else O[i-1,j-1,k-1].
// Diagonal neighbor via double-buffered 33x33 smem (boundaries stay h0).
__global__ void __launch_bounds__(1024)
scan_kernel(const float* __restrict__ h0v)
{
    __shared__ float buf[2][33 * 33];

    const int tid = threadIdx.x;
    const int j = tid >> 5, k = tid & 31;
    const int bc = blockIdx.x;                 // 0..63 = b*32+c
    const int b = bc >> 5, c = bc & 31;
    const int n = blockIdx.y;

    const int di = (n & 4) ? 1 : -1;
    const int dj = (n & 2) ? 1 : -1;
    const int dk = (n & 1) ? 1 : -1;

    const int jp = (dj > 0) ? j : 31 - j;
    const int kp = (dk > 0) ? k : 31 - k;
    const int jk = jp * 32 + kp;
    const int istep = (di > 0) ? 1024 : -1024;
    const int ibase = (di > 0) ? 0 : 31 * 1024;

    const size_t colb = (size_t)b * NSP;
    __half* hbp       = g_Ch + (size_t)(n * 96 +  0 + c) * NROW + colb + jk;
    const __half* zp  = g_Ch + (size_t)(n * 96 + 32 + c) * NROW + colb + jk;
    const __half* sp  = g_Ch + (size_t)(n * 96 + 64 + c) * NROW + colb + jk;

    const float h0 = h0v[n * 32 + c];
    // init both buffers fully to h0 (boundary rows/cols never rewritten)
    for (int i = tid; i < 33 * 33; i += 1024) { buf[0][i] = h0; buf[1][i] = h0; }
    __syncthreads();

    const int rd = j * 33 + k;                 // read slot  [j][k]
    const int wr = (j + 1) * 33 + (k + 1);     // write slot [j+1][k+1]

    int idx = ibase;
    float z  = __half2float(zp[idx]);
    float hb = __half2float(hbp[idx]);
    float s  = __half2float(sp[idx]);

    int p = 0;
#pragma unroll 4
    for (int i = 0; i < 32; ++i) {
        const int nidx = idx + istep;
        float nz = 0.f, nhb = 0.f, ns = 0.f;
        if (i < 31) {                           // prefetch next slab (no h dep)
            nz = __half2float(zp[nidx]);
            nhb = __half2float(hbp[nidx]);
            ns = __half2float(sp[nidx]);
        }
        const float prev = buf[p][rd];
        const float h = fmaf(z, hb - prev, prev);
        hbp[idx] = __float2half(h * s);         // contrib in place of hb
        buf[p ^ 1][wr] = h;
        __syncthreads();
        p ^= 1;
        idx = nidx; z = nz; hb = nhb; s = ns;
    }
}

// ---------------- 5) reduce (fp16 in, fp32 out) ------------------------------
__global__ void reduce_kernel(float* __restrict__ out)
{
    const int e4 = blockIdx.x * 256 + threadIdx.x;
    const int b = e4 >> 18;
    const int c = (e4 >> 13) & 31;
    const int sp4 = e4 & 8191;
    const size_t col = ((size_t)b * NSP + sp4 * 4);
    float2 a01 = make_float2(0.f, 0.f), a23 = make_float2(0.f, 0.f);
#pragma unroll
    for (int n = 0; n < 8; ++n) {
        const __half2* p = (const __half2*)(g_Ch + (size_t)(n * 96 + c) * NROW + col);
        float2 v0 = __half22float2(p[0]);
        float2 v1 = __half22float2(p[1]);
        a01.x += v0.x; a01.y += v0.y; a23.x += v1.x; a23.y += v1.y;
    }
    *(float4*)(out + (((size_t)b * 32 + c) * NSP + sp4 * 4)) =
        make_float4(a01.x, a01.y, a23.x, a23.y);
}

// ---------------- launch -------------------------------------------------------
extern "C" void kernel_launch(void* const* d_in, const int* in_sizes, int n_in,
                              void* d_out, int out_size)
{
    const float* x   = (const float*)d_in[0];
    const float* Wh  = (const float*)d_in[1];
    const float* bh  = (const float*)d_in[2];
    const float* Wz  = (const float*)d_in[3];
    const float* bz  = (const float*)d_in[4];
    const float* Ws  = (const float*)d_in[5];
    const float* bs  = (const float*)d_in[6];
    const float* h0v = (const float*)d_in[7];
    float* out = (float*)d_out;

    cudaFuncSetAttribute(gemm_kernel, cudaFuncAttributeMaxDynamicSharedMemorySize, GEMM_SMEM);

    wprep_kernel<<<MTOT, 256>>>(Wh, bh, Wz, bz, Ws, bs);
    xprep_kernel<<<2048, 256>>>(x);
    gemm_kernel<<<dim3(6, 512), 256, GEMM_SMEM>>>();
    scan_kernel<<<dim3(64, 8), 1024>>>(h0v);
    reduce_kernel<<<2048, 256>>>(out);
}